// round 2
// baseline (speedup 1.0000x reference)
#include <cuda_runtime.h>
#include <math.h>

// out[b,c,p,n,q] = sum_h C[n,h] * x[b,c,p,h,q]  for p<26,q<26 ; else 0.
// C (32x64) = (M32^3)^T[:, :26] @ (M64^3)[:26, :]   (host-computed in double)

struct CtParam { float ct[64][32]; };   // ct[h][n]  (transposed for vector a-frag loads)

#define TPB 256

__global__ void __launch_bounds__(TPB) spectral_pool_kernel(
    const float* __restrict__ x, float* __restrict__ out,
    const __grid_constant__ CtParam cp)
{
    __shared__ float sC[64][32];        // 8 KB
    __shared__ float sX[8][16][32];     // 16 KB : [p_local][h_chunk][q]

    const int tid = threadIdx.x;
    const int bc  = blockIdx.x >> 2;    // 0..255  (b*32+c)
    const int pt  = blockIdx.x & 3;     // p tile of 8 -> p in [pt*8, pt*8+8)

    // param -> smem (2 x float4 per thread)
    {
        const float4* src = reinterpret_cast<const float4*>(&cp.ct[0][0]);
        float4* dst = reinterpret_cast<float4*>(&sC[0][0]);
        dst[tid]       = src[tid];
        dst[tid + 256] = src[tid + 256];
    }

    // thread tile: 4 n-rows x 8 q-cols
    const int ng = tid & 7;             // 8 n-groups
    const int n0 = ng * 4;
    const int cg = tid >> 3;            // 32 col-groups
    const int pl = cg >> 2;             // p_local 0..7
    const int q0 = (cg & 3) * 8;        // q0 in {0,8,16,24}
    const int p  = pt * 8 + pl;

    const float* xb = x + (size_t)bc * 262144 + (size_t)(pt * 8) * 4096;

    float acc[4][8];
#pragma unroll
    for (int r = 0; r < 4; r++)
#pragma unroll
        for (int c = 0; c < 8; c++) acc[r][c] = 0.f;

    for (int kc = 0; kc < 4; kc++) {    // h chunks of 16
        __syncthreads();                // sX reuse guard (covers sC fill on kc=0)
        // load chunk: 8p x 16h x 32q ; truncation (q>=26 or p>=26) -> 0
#pragma unroll
        for (int it = 0; it < 16; it++) {
            int i   = tid + it * TPB;   // 0..4095
            int q   = i & 31;
            int row = i >> 5;           // 0..127
            int pll = row >> 4;
            int h   = row & 15;
            int pg  = pt * 8 + pll;
            float v = 0.f;
            if (q < 26 && pg < 26)
                v = xb[(size_t)pll * 4096 + (size_t)(kc * 16 + h) * 64 + q];
            (&sX[0][0][0])[i] = v;
        }
        __syncthreads();
#pragma unroll
        for (int k = 0; k < 16; k++) {
            float4 a  = *reinterpret_cast<const float4*>(&sC[kc * 16 + k][n0]);
            float4 b0 = *reinterpret_cast<const float4*>(&sX[pl][k][q0]);
            float4 b1 = *reinterpret_cast<const float4*>(&sX[pl][k][q0 + 4]);
            float av[4] = {a.x, a.y, a.z, a.w};
            float bv[8] = {b0.x, b0.y, b0.z, b0.w, b1.x, b1.y, b1.z, b1.w};
#pragma unroll
            for (int r = 0; r < 4; r++)
#pragma unroll
                for (int c = 0; c < 8; c++)
                    acc[r][c] = fmaf(av[r], bv[c], acc[r][c]);
        }
    }

    // store 4 rows x 8 cols (zeros in pad region come out naturally)
    float* ob = out + (size_t)bc * 32768 + (size_t)p * 1024;
#pragma unroll
    for (int r = 0; r < 4; r++) {
        float4 v0 = make_float4(acc[r][0], acc[r][1], acc[r][2], acc[r][3]);
        float4 v1 = make_float4(acc[r][4], acc[r][5], acc[r][6], acc[r][7]);
        *reinterpret_cast<float4*>(ob + (size_t)(n0 + r) * 32 + q0)     = v0;
        *reinterpret_cast<float4*>(ob + (size_t)(n0 + r) * 32 + q0 + 4) = v1;
    }
}

// ---------------- host side ----------------

static void mm_d(const double* A, const double* B, double* C, int n)
{
    for (int i = 0; i < n; i++)
        for (int j = 0; j < n; j++) {
            double s = 0.0;
            for (int k = 0; k < n; k++) s += A[i * n + k] * B[k * n + j];
            C[i * n + j] = s;
        }
}

static void build_ct(CtParam* cp)
{
    // static (no guards): recomputed deterministically every call; host cost
    // only hits the correctness call + capture call, never the timed replays.
    static double M64[64 * 64], T64[64 * 64], P64[64 * 64];
    static double M32[32 * 32], T32[32 * 32], P32[32 * 32];

    const double PI = 3.14159265358979323846;
    for (int k = 0; k < 64; k++)
        for (int n = 0; n < 64; n++) {
            double v = sqrt(2.0 / 64.0) * cos(PI * (2.0 * n + 1.0) * k / 128.0);
            if (k == 0) v = 1.0 / 8.0;                 // 1/sqrt(64)
            M64[k * 64 + n] = v;
        }
    for (int k = 0; k < 32; k++)
        for (int n = 0; n < 32; n++) {
            double v = sqrt(2.0 / 32.0) * cos(PI * (2.0 * n + 1.0) * k / 64.0);
            if (k == 0) v = 1.0 / sqrt(32.0);
            M32[k * 32 + n] = v;
        }

    mm_d(M64, M64, T64, 64);
    mm_d(T64, M64, P64, 64);     // P64 = M64^3
    mm_d(M32, M32, T32, 32);
    mm_d(T32, M32, P32, 32);     // P32 = M32^3

    // C[n][h] = sum_{k<26} P32[k][n] * P64[k][h]  -> stored transposed ct[h][n]
    for (int n = 0; n < 32; n++)
        for (int h = 0; h < 64; h++) {
            double s = 0.0;
            for (int k = 0; k < 26; k++)
                s += P32[k * 32 + n] * P64[k * 64 + h];
            cp->ct[h][n] = (float)s;
        }
}

extern "C" void kernel_launch(void* const* d_in, const int* in_sizes, int n_in,
                              void* d_out, int out_size)
{
    (void)in_sizes; (void)n_in; (void)out_size;
    const float* x = (const float*)d_in[0];
    float* out = (float*)d_out;

    static CtParam cp;          // 8 KB kernel parameter (CUDA >= 12.1 32KB limit)
    build_ct(&cp);

    // grid: 256 (b*c) x 4 p-tiles ; covers the full 32^3 output incl. zero pad
    spectral_pool_kernel<<<1024, TPB>>>(x, out, cp);
}

// round 5
// speedup vs baseline: 1.6761x; 1.6761x over previous
#include <cuda_runtime.h>
#include <math.h>

// out[b,c,p,n,q] = sum_h C[n,h] * x[b,c,p,h,q]  for p<26,q<26 ; else 0.
// C (32x64) = (M32^3)^T[:, :26] @ (M64^3)[:26, :]   (host-computed in double)

struct CtParam { float ct[64][32]; };   // ct[h][n]

#define TPB 256

// packed fp32x2 FMA (sm_100+): d.lo += a.lo*b.lo ; d.hi += a.hi*b.hi
#define FMA2(d, a, b) asm("fma.rn.f32x2 %0, %1, %2, %0;" : "+l"(d) : "l"(a), "l"(b))
// duplicate one fp32 into both halves of a 64-bit pair
#define DUP2(d, f)    asm("mov.b64 %0, {%1, %1};" : "=l"(d) : "f"(f))

__global__ void __launch_bounds__(TPB) spectral_pool_kernel(
    const float* __restrict__ x, float* __restrict__ out,
    const __grid_constant__ CtParam cp)
{
    __shared__ float sC[64][32];            // 8 KB
    __shared__ float sX[2][8][16][32];      // 32 KB double-buffered [p][h][q]

    const int tid = threadIdx.x;
    const int bc  = blockIdx.x >> 2;        // 0..255  (b*32+c)
    const int pt  = blockIdx.x & 3;         // p-tile of 8

    // param -> smem
    {
        const float4* src = reinterpret_cast<const float4*>(&cp.ct[0][0]);
        float4* dst = reinterpret_cast<float4*>(&sC[0][0]);
        dst[tid]       = src[tid];
        dst[tid + 256] = src[tid + 256];
    }

    // ---- load decomposition (fixed per thread): 4 float4 per chunk ----
    const int q4    = tid & 7;              // float4 slot within 32-q row
    const int hq    = (tid >> 3) & 15;      // h within 16-chunk
    const int pbase = tid >> 7;             // pll = pbase + 2*j
    const bool ldq  = (q4 < 7);             // slot 7 (q 28..31) always zero

    // ---- compute decomposition: 4 n-rows x 8 q-cols per thread ----
    const int n0 = (tid & 7) * 4;
    const int cg = tid >> 3;
    const int pl = cg >> 2;                 // p_local 0..7
    const int q0 = (cg & 3) * 8;

    const float* xb = x + (size_t)bc * 262144 + (size_t)(pt * 8) * 4096;

    unsigned long long acc[4][4];           // 4n x 4 q-pairs (f32x2)
#pragma unroll
    for (int r = 0; r < 4; r++)
#pragma unroll
        for (int c = 0; c < 4; c++) acc[r][c] = 0ull;

    float4 v[4];

    // prologue: load + store chunk 0
#pragma unroll
    for (int j = 0; j < 4; j++) {
        int pll = pbase + 2 * j;
        v[j] = make_float4(0.f, 0.f, 0.f, 0.f);
        if (ldq && (pt * 8 + pll) < 26)
            v[j] = *reinterpret_cast<const float4*>(
                xb + (size_t)pll * 4096 + (size_t)hq * 64 + q4 * 4);
        if (q4 == 6) { v[j].z = 0.f; v[j].w = 0.f; }
    }
#pragma unroll
    for (int j = 0; j < 4; j++)
        *reinterpret_cast<float4*>(&sX[0][pbase + 2 * j][hq][q4 * 4]) = v[j];
    __syncthreads();

#pragma unroll
    for (int kc = 0; kc < 4; kc++) {
        // issue next chunk's global loads early (latency hidden by compute)
        if (kc < 3) {
#pragma unroll
            for (int j = 0; j < 4; j++) {
                int pll = pbase + 2 * j;
                v[j] = make_float4(0.f, 0.f, 0.f, 0.f);
                if (ldq && (pt * 8 + pll) < 26)
                    v[j] = *reinterpret_cast<const float4*>(
                        xb + (size_t)pll * 4096 +
                        (size_t)((kc + 1) * 16 + hq) * 64 + q4 * 4);
                if (q4 == 6) { v[j].z = 0.f; v[j].w = 0.f; }
            }
        }

        const int buf = kc & 1;
#pragma unroll
        for (int k = 0; k < 16; k++) {
            float4 a = *reinterpret_cast<const float4*>(&sC[kc * 16 + k][n0]);
            ulonglong2 b0 = *reinterpret_cast<const ulonglong2*>(&sX[buf][pl][k][q0]);
            ulonglong2 b1 = *reinterpret_cast<const ulonglong2*>(&sX[buf][pl][k][q0 + 4]);
            unsigned long long bv[4] = {b0.x, b0.y, b1.x, b1.y};
            float av[4] = {a.x, a.y, a.z, a.w};
#pragma unroll
            for (int r = 0; r < 4; r++) {
                unsigned long long ap;
                DUP2(ap, av[r]);
#pragma unroll
                for (int c = 0; c < 4; c++) FMA2(acc[r][c], ap, bv[c]);
            }
        }

        if (kc < 3) {
#pragma unroll
            for (int j = 0; j < 4; j++)
                *reinterpret_cast<float4*>(
                    &sX[buf ^ 1][pbase + 2 * j][hq][q4 * 4]) = v[j];
            __syncthreads();
        }
    }

    // store 4 rows x 8 cols (pad region is naturally exact zero)
    float* ob = out + (size_t)bc * 32768 + (size_t)(pt * 8 + pl) * 1024;
#pragma unroll
    for (int r = 0; r < 4; r++) {
        ulonglong2 s0, s1;
        s0.x = acc[r][0]; s0.y = acc[r][1];
        s1.x = acc[r][2]; s1.y = acc[r][3];
        *reinterpret_cast<ulonglong2*>(ob + (size_t)(n0 + r) * 32 + q0)     = s0;
        *reinterpret_cast<ulonglong2*>(ob + (size_t)(n0 + r) * 32 + q0 + 4) = s1;
    }
}

// ---------------- host side ----------------

static void mm_d(const double* A, const double* B, double* C, int n)
{
    for (int i = 0; i < n; i++)
        for (int j = 0; j < n; j++) {
            double s = 0.0;
            for (int k = 0; k < n; k++) s += A[i * n + k] * B[k * n + j];
            C[i * n + j] = s;
        }
}

static void build_ct(CtParam* cp)
{
    static double M64[64 * 64], T64[64 * 64], P64[64 * 64];
    static double M32[32 * 32], T32[32 * 32], P32[32 * 32];

    const double PI = 3.14159265358979323846;
    for (int k = 0; k < 64; k++)
        for (int n = 0; n < 64; n++) {
            double v = sqrt(2.0 / 64.0) * cos(PI * (2.0 * n + 1.0) * k / 128.0);
            if (k == 0) v = 1.0 / 8.0;
            M64[k * 64 + n] = v;
        }
    for (int k = 0; k < 32; k++)
        for (int n = 0; n < 32; n++) {
            double v = sqrt(2.0 / 32.0) * cos(PI * (2.0 * n + 1.0) * k / 64.0);
            if (k == 0) v = 1.0 / sqrt(32.0);
            M32[k * 32 + n] = v;
        }

    mm_d(M64, M64, T64, 64);
    mm_d(T64, M64, P64, 64);     // M64^3
    mm_d(M32, M32, T32, 32);
    mm_d(T32, M32, P32, 32);     // M32^3

    for (int n = 0; n < 32; n++)
        for (int h = 0; h < 64; h++) {
            double s = 0.0;
            for (int k = 0; k < 26; k++)
                s += P32[k * 32 + n] * P64[k * 64 + h];
            cp->ct[h][n] = (float)s;
        }
}

extern "C" void kernel_launch(void* const* d_in, const int* in_sizes, int n_in,
                              void* d_out, int out_size)
{
    (void)in_sizes; (void)n_in; (void)out_size;
    const float* x = (const float*)d_in[0];
    float* out = (float*)d_out;

    static CtParam cp;
    build_ct(&cp);

    spectral_pool_kernel<<<1024, TPB>>>(x, out, cp);
}